// round 1
// baseline (speedup 1.0000x reference)
#include <cuda_runtime.h>
#include <cuda_bf16.h>
#include <math.h>

// Problem constants
#define BB 4
#define SS 2048
#define DD 1024
#define HH 16
#define DKK 64
#define MM (BB * SS)   // 8192

// ---------------- scratch (device globals; no runtime alloc allowed) --------
__device__ float g_qp[(size_t)MM * DD];
__device__ float g_kp[(size_t)MM * DD];
__device__ float g_vp[(size_t)MM * DD];
__device__ float g_ao[(size_t)MM * DD];

// ---------------- SGEMM: C[M,N] = A[M,K] @ W[K,N] + bias[N] -----------------
// Tile 128x128, K-tile 8, 256 threads, 8x8 per-thread microtile.
#define TM 128
#define TN 128
#define TKK 8

__global__ void __launch_bounds__(256, 2)
sgemm_bias(const float* __restrict__ A, const float* __restrict__ W,
           const float* __restrict__ bias, float* __restrict__ C,
           int Mdim, int Ndim, int Kdim) {
    __shared__ float As[TKK][TM];   // transposed A tile
    __shared__ float Bs[TKK][TN];

    const int tid = threadIdx.x;
    const int bm = blockIdx.y * TM;
    const int bn = blockIdx.x * TN;

    // A-tile load mapping: 128 rows x 8 cols = 256 float4 (one per thread)
    const int arow = tid >> 1;
    const int acol = (tid & 1) * 4;
    // B-tile load mapping: 8 rows x 128 cols = 256 float4
    const int brow = tid >> 5;
    const int bcol = (tid & 31) * 4;

    const int ty = tid >> 4;        // 0..15
    const int tx = tid & 15;        // 0..15
    const int row0 = ty * 8;
    const int col0 = tx * 8;

    float acc[8][8];
#pragma unroll
    for (int i = 0; i < 8; i++)
#pragma unroll
        for (int j = 0; j < 8; j++) acc[i][j] = 0.0f;

    const float* aptr = A + (size_t)(bm + arow) * Kdim + acol;
    const float* bptr = W + (size_t)brow * Ndim + bn + bcol;

    for (int k0 = 0; k0 < Kdim; k0 += TKK) {
        float4 av = *(const float4*)(aptr + k0);
        As[acol + 0][arow] = av.x;
        As[acol + 1][arow] = av.y;
        As[acol + 2][arow] = av.z;
        As[acol + 3][arow] = av.w;
        float4 bv = *(const float4*)(bptr + (size_t)k0 * Ndim);
        *(float4*)&Bs[brow][bcol] = bv;
        __syncthreads();

#pragma unroll
        for (int kk = 0; kk < TKK; kk++) {
            float a[8], b[8];
            *(float4*)&a[0] = *(const float4*)&As[kk][row0];
            *(float4*)&a[4] = *(const float4*)&As[kk][row0 + 4];
            *(float4*)&b[0] = *(const float4*)&Bs[kk][col0];
            *(float4*)&b[4] = *(const float4*)&Bs[kk][col0 + 4];
#pragma unroll
            for (int i = 0; i < 8; i++)
#pragma unroll
                for (int j = 0; j < 8; j++)
                    acc[i][j] = fmaf(a[i], b[j], acc[i][j]);
        }
        __syncthreads();
    }

    // epilogue: add bias, store
    float bb[8];
#pragma unroll
    for (int j = 0; j < 8; j++) bb[j] = bias[bn + col0 + j];

#pragma unroll
    for (int i = 0; i < 8; i++) {
        float* crow = C + (size_t)(bm + row0 + i) * Ndim + bn + col0;
        float4 o0, o1;
        o0.x = acc[i][0] + bb[0];
        o0.y = acc[i][1] + bb[1];
        o0.z = acc[i][2] + bb[2];
        o0.w = acc[i][3] + bb[3];
        o1.x = acc[i][4] + bb[4];
        o1.y = acc[i][5] + bb[5];
        o1.z = acc[i][6] + bb[6];
        o1.w = acc[i][7] + bb[7];
        *(float4*)(crow) = o0;
        *(float4*)(crow + 4) = o1;
    }
}

// ---------------- Flash attention (fp32, online softmax) --------------------
// Per CTA: one (b, h, 64-query block). BQ=BK=64, DK=64, 256 threads,
// each thread owns a 4x4 tile of scores/output.
#define BQ 64
#define BK 64
#define LDPAD 68   // row stride in floats (64 + 4 pad, keeps float4 alignment)

__global__ void __launch_bounds__(256, 2)
flash_attn(const float* __restrict__ Qp, const float* __restrict__ Kp,
           const float* __restrict__ Vp, float* __restrict__ Op) {
    extern __shared__ float smem[];
    float* Qs = smem;                   // [64][68]
    float* Ks = Qs + BQ * LDPAD;        // [64][68]
    float* Vs = Ks + BK * LDPAD;        // [64][68]
    float* Ps = Vs + BK * LDPAD;        // [64][68]

    const int tid = threadIdx.x;
    const int qb = blockIdx.x;          // 0..S/BQ-1
    const int h  = blockIdx.y;
    const int b  = blockIdx.z;
    const int q0 = qb * BQ;
    const float scale = 0.125f;         // 1/sqrt(64)

    const size_t base = (size_t)b * SS * DD + (size_t)h * DKK;

    // load Q tile: 64 rows x 16 float4
    for (int i = tid; i < BQ * 16; i += 256) {
        int r = i >> 4;
        int c4 = (i & 15) * 4;
        float4 v = *(const float4*)(Qp + base + (size_t)(q0 + r) * DD + c4);
        *(float4*)&Qs[r * LDPAD + c4] = v;
    }

    const int ty = tid >> 4;
    const int tx = tid & 15;
    const int i0 = ty * 4;              // score/output row base
    const int j0 = tx * 4;              // score col base / output col base

    float m_i[4], l_i[4], Oacc[4][4];
#pragma unroll
    for (int r = 0; r < 4; r++) {
        m_i[r] = -1e30f;
        l_i[r] = 0.0f;
#pragma unroll
        for (int c = 0; c < 4; c++) Oacc[r][c] = 0.0f;
    }

    for (int kb = 0; kb < SS / BK; kb++) {
        __syncthreads();   // protect Ks/Vs/Ps reuse (and Qs on first iter)
        // load K and V tiles
        for (int i = tid; i < BK * 16; i += 256) {
            int r = i >> 4;
            int c4 = (i & 15) * 4;
            size_t goff = base + (size_t)(kb * BK + r) * DD + c4;
            float4 kv = *(const float4*)(Kp + goff);
            *(float4*)&Ks[r * LDPAD + c4] = kv;
            float4 vv = *(const float4*)(Vp + goff);
            *(float4*)&Vs[r * LDPAD + c4] = vv;
        }
        __syncthreads();

        // scores: sc[r][c] = sum_d Q[i0+r][d] * K[j0+c][d]
        float sc[4][4];
#pragma unroll
        for (int r = 0; r < 4; r++)
#pragma unroll
            for (int c = 0; c < 4; c++) sc[r][c] = 0.0f;

#pragma unroll
        for (int d = 0; d < DKK; d += 4) {
            float4 qv[4], kv[4];
#pragma unroll
            for (int r = 0; r < 4; r++)
                qv[r] = *(const float4*)&Qs[(i0 + r) * LDPAD + d];
#pragma unroll
            for (int c = 0; c < 4; c++)
                kv[c] = *(const float4*)&Ks[(j0 + c) * LDPAD + d];
#pragma unroll
            for (int r = 0; r < 4; r++)
#pragma unroll
                for (int c = 0; c < 4; c++) {
                    sc[r][c] = fmaf(qv[r].x, kv[c].x, sc[r][c]);
                    sc[r][c] = fmaf(qv[r].y, kv[c].y, sc[r][c]);
                    sc[r][c] = fmaf(qv[r].z, kv[c].z, sc[r][c]);
                    sc[r][c] = fmaf(qv[r].w, kv[c].w, sc[r][c]);
                }
        }

        // online softmax per row (reduce across the 16 tx lanes of each row)
#pragma unroll
        for (int r = 0; r < 4; r++) {
#pragma unroll
            for (int c = 0; c < 4; c++) sc[r][c] *= scale;
            float rm = fmaxf(fmaxf(sc[r][0], sc[r][1]), fmaxf(sc[r][2], sc[r][3]));
#pragma unroll
            for (int off = 8; off > 0; off >>= 1)
                rm = fmaxf(rm, __shfl_xor_sync(0xffffffffu, rm, off));
            float mnew = fmaxf(m_i[r], rm);
            float corr = expf(m_i[r] - mnew);
            float rs = 0.0f;
#pragma unroll
            for (int c = 0; c < 4; c++) {
                sc[r][c] = expf(sc[r][c] - mnew);
                rs += sc[r][c];
            }
#pragma unroll
            for (int off = 8; off > 0; off >>= 1)
                rs += __shfl_xor_sync(0xffffffffu, rs, off);
            l_i[r] = l_i[r] * corr + rs;
            m_i[r] = mnew;
#pragma unroll
            for (int c = 0; c < 4; c++) Oacc[r][c] *= corr;
        }

        // write P to smem
#pragma unroll
        for (int r = 0; r < 4; r++) {
            float4 p4 = make_float4(sc[r][0], sc[r][1], sc[r][2], sc[r][3]);
            *(float4*)&Ps[(i0 + r) * LDPAD + j0] = p4;
        }
        __syncthreads();

        // O += P @ V   (thread owns output cols j0..j0+3)
#pragma unroll 4
        for (int j = 0; j < BK; j++) {
            float4 vv = *(const float4*)&Vs[j * LDPAD + j0];
            float p[4];
#pragma unroll
            for (int r = 0; r < 4; r++) p[r] = Ps[(i0 + r) * LDPAD + j];
#pragma unroll
            for (int r = 0; r < 4; r++) {
                Oacc[r][0] = fmaf(p[r], vv.x, Oacc[r][0]);
                Oacc[r][1] = fmaf(p[r], vv.y, Oacc[r][1]);
                Oacc[r][2] = fmaf(p[r], vv.z, Oacc[r][2]);
                Oacc[r][3] = fmaf(p[r], vv.w, Oacc[r][3]);
            }
        }
    }

    // epilogue: normalize, write to [B,S,D] layout at head offset
#pragma unroll
    for (int r = 0; r < 4; r++) {
        float inv = 1.0f / l_i[r];
        float4 o = make_float4(Oacc[r][0] * inv, Oacc[r][1] * inv,
                               Oacc[r][2] * inv, Oacc[r][3] * inv);
        *(float4*)(Op + base + (size_t)(q0 + i0 + r) * DD + j0) = o;
    }
}

// ---------------- launch -----------------------------------------------------
extern "C" void kernel_launch(void* const* d_in, const int* in_sizes, int n_in,
                              void* d_out, int out_size) {
    (void)in_sizes; (void)n_in; (void)out_size;
    const float* q  = (const float*)d_in[0];
    const float* k  = (const float*)d_in[1];
    const float* v  = (const float*)d_in[2];
    const float* Wq = (const float*)d_in[3];
    const float* bq = (const float*)d_in[4];
    const float* Wk = (const float*)d_in[5];
    const float* bk = (const float*)d_in[6];
    const float* Wv = (const float*)d_in[7];
    const float* bv = (const float*)d_in[8];
    const float* Wo = (const float*)d_in[9];
    const float* bo = (const float*)d_in[10];
    float* out = (float*)d_out;

    float *qp, *kp, *vp, *ao;
    cudaGetSymbolAddress((void**)&qp, g_qp);
    cudaGetSymbolAddress((void**)&kp, g_kp);
    cudaGetSymbolAddress((void**)&vp, g_vp);
    cudaGetSymbolAddress((void**)&ao, g_ao);

    const int smem_bytes = 4 * BQ * LDPAD * (int)sizeof(float);  // 69632
    cudaFuncSetAttribute(flash_attn, cudaFuncAttributeMaxDynamicSharedMemorySize,
                         smem_bytes);

    dim3 gemm_grid(DD / TN, MM / TM);   // (8, 64)
    sgemm_bias<<<gemm_grid, 256>>>(q, Wq, bq, qp, MM, DD, DD);
    sgemm_bias<<<gemm_grid, 256>>>(k, Wk, bk, kp, MM, DD, DD);
    sgemm_bias<<<gemm_grid, 256>>>(v, Wv, bv, vp, MM, DD, DD);

    dim3 attn_grid(SS / BQ, HH, BB);    // (32, 16, 4)
    flash_attn<<<attn_grid, 256, smem_bytes>>>(qp, kp, vp, ao);

    sgemm_bias<<<gemm_grid, 256>>>(ao, Wo, bo, out, MM, DD, DD);
}

// round 3
// speedup vs baseline: 4.2856x; 4.2856x over previous
#include <cuda_runtime.h>
#include <cuda_bf16.h>
#include <math.h>
#include <stdint.h>

// Problem constants
#define BB 4
#define SS 2048
#define DD 1024
#define HH 16
#define DKK 64
#define MM (BB * SS)   // 8192
#define GK 1024

// ---------------- scratch (device globals; no runtime alloc allowed) --------
__device__ float g_qp[(size_t)MM * DD];
__device__ float g_kp[(size_t)MM * DD];
__device__ float g_vp[(size_t)MM * DD];
__device__ float g_ao[(size_t)MM * DD];

// ==================== helpers ================================================
__device__ __forceinline__ uint32_t f2tf32(float x) {
    uint32_t u;
    asm("cvt.rna.tf32.f32 %0, %1;" : "=r"(u) : "f"(x));
    return u;
}

// m16n8k8 tf32 mma (legacy tensor core; valid on compute_103 virtual arch)
__device__ __forceinline__ void mma_tf32(float* c, const uint32_t* a,
                                         const uint32_t* b) {
    asm volatile(
        "mma.sync.aligned.m16n8k8.row.col.f32.tf32.tf32.f32 "
        "{%0,%1,%2,%3}, {%4,%5,%6,%7}, {%8,%9}, {%0,%1,%2,%3};"
        : "+f"(c[0]), "+f"(c[1]), "+f"(c[2]), "+f"(c[3])
        : "r"(a[0]), "r"(a[1]), "r"(a[2]), "r"(a[3]), "r"(b[0]), "r"(b[1]));
}

// ==================== GEMM: C[M,N] = A[M,K] @ W[K,N] + bias ================
// CTA 128x128, 8 warps as 4x2 (warp tile 32x64), K-chunk 32, double buffer.
// Fragment maps (PTX m16n8k8 tf32):
//   A (row major): a0=(g,t) a1=(g+8,t) a2=(g,t+4) a3=(g+8,t+4)   g=lane>>2,t=lane&3
//   B (col major): b0=(k=t, n=g) b1=(k=t+4, n=g)
//   C: c0=(g,2t) c1=(g,2t+1) c2=(g+8,2t) c3=(g+8,2t+1)
#define GTM 128
#define GTN 128
#define GKC 32
#define ALD 36     // A smem row stride (floats): banks (4m+k)%32 unique
#define BLD 136    // B smem row stride: banks (8k+n)%32 unique
#define ABUF (GTM * ALD)
#define BBUF (GKC * BLD)
#define GSM_FLOATS (2 * (ABUF + BBUF))   // 17920 floats = 71680 B

__global__ void __launch_bounds__(256)
gemm_mma(const float* __restrict__ A, const float* __restrict__ W,
         const float* __restrict__ bias, float* __restrict__ C) {
    extern __shared__ __align__(16) uint32_t gsm[];

    const int tid = threadIdx.x;
    const int wid = tid >> 5, lane = tid & 31;
    const int gid = lane >> 2, tg = lane & 3;
    const int bm = blockIdx.y * GTM, bn = blockIdx.x * GTN;
    const int wm = (wid >> 1) * 32, wn = (wid & 1) * 64;

    float acc[2][8][4];
#pragma unroll
    for (int mt = 0; mt < 2; mt++)
#pragma unroll
        for (int nt = 0; nt < 8; nt++)
#pragma unroll
            for (int c = 0; c < 4; c++) acc[mt][nt][c] = 0.0f;

    // global load mapping
    const int arow = tid >> 3, acol = (tid & 7) * 4;   // +32 rows per iter
    const int brow = tid >> 5, bcol = (tid & 31) * 4;  // +8 rows per iter

    float4 ar[4], br[4];

    auto loadAB = [&](int kc) {
        const float* ap = A + (size_t)(bm + arow) * GK + kc * GKC + acol;
#pragma unroll
        for (int i = 0; i < 4; i++)
            ar[i] = *(const float4*)(ap + (size_t)(32 * i) * GK);
        const float* bp = W + (size_t)(kc * GKC + brow) * DD + bn + bcol;
#pragma unroll
        for (int i = 0; i < 4; i++)
            br[i] = *(const float4*)(bp + (size_t)(8 * i) * DD);
    };

    auto storeAB = [&](int buf) {
        uint32_t* As = gsm + buf * ABUF;
        uint32_t* Bs = gsm + 2 * ABUF + buf * BBUF;
#pragma unroll
        for (int i = 0; i < 4; i++) {
            uint32_t* p = As + (arow + 32 * i) * ALD + acol;
            p[0] = f2tf32(ar[i].x); p[1] = f2tf32(ar[i].y);
            p[2] = f2tf32(ar[i].z); p[3] = f2tf32(ar[i].w);
        }
#pragma unroll
        for (int i = 0; i < 4; i++) {
            uint32_t* p = Bs + (brow + 8 * i) * BLD + bcol;
            p[0] = f2tf32(br[i].x); p[1] = f2tf32(br[i].y);
            p[2] = f2tf32(br[i].z); p[3] = f2tf32(br[i].w);
        }
    };

    auto compute = [&](int buf) {
        const uint32_t* As = gsm + buf * ABUF;
        const uint32_t* Bs = gsm + 2 * ABUF + buf * BBUF;
#pragma unroll
        for (int ks = 0; ks < 4; ks++) {
            const int k0 = ks * 8;
            uint32_t af[2][4], bf[8][2];
#pragma unroll
            for (int mt = 0; mt < 2; mt++) {
                const uint32_t* p = As + (wm + mt * 16 + gid) * ALD + k0 + tg;
                af[mt][0] = p[0];
                af[mt][1] = p[8 * ALD];
                af[mt][2] = p[4];
                af[mt][3] = p[8 * ALD + 4];
            }
#pragma unroll
            for (int nt = 0; nt < 8; nt++) {
                const uint32_t* p = Bs + (k0 + tg) * BLD + wn + nt * 8 + gid;
                bf[nt][0] = p[0];
                bf[nt][1] = p[4 * BLD];
            }
#pragma unroll
            for (int mt = 0; mt < 2; mt++)
#pragma unroll
                for (int nt = 0; nt < 8; nt++)
                    mma_tf32(acc[mt][nt], af[mt], bf[nt]);
        }
    };

    loadAB(0);
    storeAB(0);
    __syncthreads();
    for (int kc = 0; kc < GK / GKC; kc++) {
        const int buf = kc & 1;
        if (kc < GK / GKC - 1) loadAB(kc + 1);
        compute(buf);
        if (kc < GK / GKC - 1) storeAB(buf ^ 1);
        __syncthreads();
    }

    // epilogue: bias + store
#pragma unroll
    for (int mt = 0; mt < 2; mt++) {
        const int row = bm + wm + mt * 16 + gid;
#pragma unroll
        for (int nt = 0; nt < 8; nt++) {
            const int col = bn + wn + nt * 8 + 2 * tg;
            const float b0 = __ldg(bias + col), b1 = __ldg(bias + col + 1);
            float2 v0 = make_float2(acc[mt][nt][0] + b0, acc[mt][nt][1] + b1);
            float2 v1 = make_float2(acc[mt][nt][2] + b0, acc[mt][nt][3] + b1);
            *(float2*)(C + (size_t)row * DD + col) = v0;
            *(float2*)(C + (size_t)(row + 8) * DD + col) = v1;
        }
    }
}

// ==================== Flash attention on mma.sync tf32 ======================
// CTA: one (b, h, 64-q block). 4 warps, each owns 16 q rows. BK=64 per iter.
#define FQLD 68   // Q/K/P smem stride: a-frag banks (4m+k) unique; K b-frag (4n+k) unique
#define FVLD 72   // V smem stride: b-frag banks (8k+n) unique
#define FSM_FLOATS (64 * FQLD * 3 + 64 * FVLD)   // Qs,Ks,Ps + Vs = 17664

__global__ void __launch_bounds__(128)
flash_mma(const float* __restrict__ Qp, const float* __restrict__ Kp,
          const float* __restrict__ Vp, float* __restrict__ Op) {
    extern __shared__ __align__(16) uint32_t fsm[];
    uint32_t* Qs = fsm;                    // [64][68]
    uint32_t* Ks = Qs + 64 * FQLD;         // [64][68]
    uint32_t* Vs = Ks + 64 * FQLD;         // [64][72]
    uint32_t* Ps = Vs + 64 * FVLD;         // [64][68]

    const int tid = threadIdx.x;
    const int wid = tid >> 5, lane = tid & 31;
    const int gid = lane >> 2, tg = lane & 3;
    const int q0 = blockIdx.x * 64;
    const int h = blockIdx.y, b = blockIdx.z;
    const size_t base = (size_t)b * SS * DD + (size_t)h * DKK;
    const int wm = wid * 16;

    // Load Q tile once, folding in 1/sqrt(dk)=0.125
    for (int i = tid; i < 64 * 16; i += 128) {
        const int r = i >> 4, c = (i & 15) * 4;
        float4 v = *(const float4*)(Qp + base + (size_t)(q0 + r) * DD + c);
        uint32_t* p = Qs + r * FQLD + c;
        p[0] = f2tf32(v.x * 0.125f); p[1] = f2tf32(v.y * 0.125f);
        p[2] = f2tf32(v.z * 0.125f); p[3] = f2tf32(v.w * 0.125f);
    }

    float m_i[2] = {-1e30f, -1e30f};
    float l_i[2] = {0.0f, 0.0f};
    float oacc[8][4];
#pragma unroll
    for (int nt = 0; nt < 8; nt++)
#pragma unroll
        for (int c = 0; c < 4; c++) oacc[nt][c] = 0.0f;

    for (int kb = 0; kb < SS / 64; kb++) {
        __syncthreads();   // prev PV done before overwriting Ks/Vs
        for (int i = tid; i < 64 * 16; i += 128) {
            const int r = i >> 4, c = (i & 15) * 4;
            const size_t g = base + (size_t)(kb * 64 + r) * DD + c;
            float4 kv = *(const float4*)(Kp + g);
            uint32_t* pk = Ks + r * FQLD + c;
            pk[0] = f2tf32(kv.x); pk[1] = f2tf32(kv.y);
            pk[2] = f2tf32(kv.z); pk[3] = f2tf32(kv.w);
            float4 vv = *(const float4*)(Vp + g);
            uint32_t* pv = Vs + r * FVLD + c;
            pv[0] = f2tf32(vv.x); pv[1] = f2tf32(vv.y);
            pv[2] = f2tf32(vv.z); pv[3] = f2tf32(vv.w);
        }
        __syncthreads();

        // S = Q @ K^T  (B element (k,n) = K[n][k] -> addr n*FQLD + k)
        float s[8][4];
#pragma unroll
        for (int nt = 0; nt < 8; nt++)
#pragma unroll
            for (int c = 0; c < 4; c++) s[nt][c] = 0.0f;

#pragma unroll
        for (int ks = 0; ks < 8; ks++) {
            const int k0 = ks * 8;
            uint32_t af[4];
            const uint32_t* ap = Qs + (wm + gid) * FQLD + k0 + tg;
            af[0] = ap[0];
            af[1] = ap[8 * FQLD];
            af[2] = ap[4];
            af[3] = ap[8 * FQLD + 4];
#pragma unroll
            for (int nt = 0; nt < 8; nt++) {
                uint32_t bf[2];
                const uint32_t* bp = Ks + (nt * 8 + gid) * FQLD + k0 + tg;
                bf[0] = bp[0];
                bf[1] = bp[4];
                mma_tf32(s[nt], af, bf);
            }
        }

        // online softmax (rows gid and gid+8 of this warp's 16-row tile)
        float mx0 = -1e30f, mx1 = -1e30f;
#pragma unroll
        for (int nt = 0; nt < 8; nt++) {
            mx0 = fmaxf(mx0, fmaxf(s[nt][0], s[nt][1]));
            mx1 = fmaxf(mx1, fmaxf(s[nt][2], s[nt][3]));
        }
#pragma unroll
        for (int m = 1; m <= 2; m <<= 1) {
            mx0 = fmaxf(mx0, __shfl_xor_sync(0xffffffffu, mx0, m));
            mx1 = fmaxf(mx1, __shfl_xor_sync(0xffffffffu, mx1, m));
        }
        const float mn0 = fmaxf(m_i[0], mx0);
        const float mn1 = fmaxf(m_i[1], mx1);
        const float corr0 = __expf(m_i[0] - mn0);
        const float corr1 = __expf(m_i[1] - mn1);
        float sum0 = 0.0f, sum1 = 0.0f;
#pragma unroll
        for (int nt = 0; nt < 8; nt++) {
            s[nt][0] = __expf(s[nt][0] - mn0);
            s[nt][1] = __expf(s[nt][1] - mn0);
            s[nt][2] = __expf(s[nt][2] - mn1);
            s[nt][3] = __expf(s[nt][3] - mn1);
            sum0 += s[nt][0] + s[nt][1];
            sum1 += s[nt][2] + s[nt][3];
        }
#pragma unroll
        for (int m = 1; m <= 2; m <<= 1) {
            sum0 += __shfl_xor_sync(0xffffffffu, sum0, m);
            sum1 += __shfl_xor_sync(0xffffffffu, sum1, m);
        }
        l_i[0] = l_i[0] * corr0 + sum0;
        l_i[1] = l_i[1] * corr1 + sum1;
        m_i[0] = mn0;
        m_i[1] = mn1;
#pragma unroll
        for (int nt = 0; nt < 8; nt++) {
            oacc[nt][0] *= corr0; oacc[nt][1] *= corr0;
            oacc[nt][2] *= corr1; oacc[nt][3] *= corr1;
        }

        // write P fragments (C layout) to smem as tf32
#pragma unroll
        for (int nt = 0; nt < 8; nt++) {
            uint32_t* pp = Ps + (wm + gid) * FQLD + nt * 8 + 2 * tg;
            pp[0] = f2tf32(s[nt][0]);
            pp[1] = f2tf32(s[nt][1]);
            pp[8 * FQLD] = f2tf32(s[nt][2]);
            pp[8 * FQLD + 1] = f2tf32(s[nt][3]);
        }
        __syncthreads();

        // O += P @ V  (B element (k,n) = V[k][n] -> addr k*FVLD + n)
#pragma unroll
        for (int ks = 0; ks < 8; ks++) {
            const int k0 = ks * 8;
            uint32_t af[4];
            const uint32_t* ap = Ps + (wm + gid) * FQLD + k0 + tg;
            af[0] = ap[0];
            af[1] = ap[8 * FQLD];
            af[2] = ap[4];
            af[3] = ap[8 * FQLD + 4];
#pragma unroll
            for (int nt = 0; nt < 8; nt++) {
                uint32_t bf[2];
                const uint32_t* bp = Vs + (k0 + tg) * FVLD + nt * 8 + gid;
                bf[0] = bp[0];
                bf[1] = bp[4 * FVLD];
                mma_tf32(oacc[nt], af, bf);
            }
        }
    }

    // epilogue: normalize, store
    const float inv0 = 1.0f / l_i[0];
    const float inv1 = 1.0f / l_i[1];
    const int row = q0 + wm + gid;
#pragma unroll
    for (int nt = 0; nt < 8; nt++) {
        const int col = nt * 8 + 2 * tg;
        float2 v0 = make_float2(oacc[nt][0] * inv0, oacc[nt][1] * inv0);
        float2 v1 = make_float2(oacc[nt][2] * inv1, oacc[nt][3] * inv1);
        *(float2*)(Op + base + (size_t)row * DD + col) = v0;
        *(float2*)(Op + base + (size_t)(row + 8) * DD + col) = v1;
    }
}

// ---------------- launch -----------------------------------------------------
extern "C" void kernel_launch(void* const* d_in, const int* in_sizes, int n_in,
                              void* d_out, int out_size) {
    (void)in_sizes; (void)n_in; (void)out_size;
    const float* q  = (const float*)d_in[0];
    const float* k  = (const float*)d_in[1];
    const float* v  = (const float*)d_in[2];
    const float* Wq = (const float*)d_in[3];
    const float* bq = (const float*)d_in[4];
    const float* Wk = (const float*)d_in[5];
    const float* bk = (const float*)d_in[6];
    const float* Wv = (const float*)d_in[7];
    const float* bv = (const float*)d_in[8];
    const float* Wo = (const float*)d_in[9];
    const float* bo = (const float*)d_in[10];
    float* out = (float*)d_out;

    float *qp, *kp, *vp, *ao;
    cudaGetSymbolAddress((void**)&qp, g_qp);
    cudaGetSymbolAddress((void**)&kp, g_kp);
    cudaGetSymbolAddress((void**)&vp, g_vp);
    cudaGetSymbolAddress((void**)&ao, g_ao);

    const int gsm_bytes = GSM_FLOATS * 4;   // 71680
    const int fsm_bytes = FSM_FLOATS * 4;   // 70656
    cudaFuncSetAttribute(gemm_mma, cudaFuncAttributeMaxDynamicSharedMemorySize,
                         gsm_bytes);
    cudaFuncSetAttribute(flash_mma, cudaFuncAttributeMaxDynamicSharedMemorySize,
                         fsm_bytes);

    dim3 gemm_grid(DD / GTN, MM / GTM);   // (8, 64)
    gemm_mma<<<gemm_grid, 256, gsm_bytes>>>(q, Wq, bq, qp);
    gemm_mma<<<gemm_grid, 256, gsm_bytes>>>(k, Wk, bk, kp);
    gemm_mma<<<gemm_grid, 256, gsm_bytes>>>(v, Wv, bv, vp);

    dim3 attn_grid(SS / 64, HH, BB);      // (32, 16, 4)
    flash_mma<<<attn_grid, 128, fsm_bytes>>>(qp, kp, vp, ao);

    gemm_mma<<<gemm_grid, 256, gsm_bytes>>>(ao, Wo, bo, out);
}

// round 4
// speedup vs baseline: 4.5745x; 1.0674x over previous
#include <cuda_runtime.h>
#include <cuda_bf16.h>
#include <math.h>
#include <stdint.h>

// Problem constants
#define BB 4
#define SS 2048
#define DD 1024
#define HH 16
#define DKK 64
#define MM (BB * SS)   // 8192
#define GK 1024

// ---------------- scratch (device globals; no runtime alloc allowed) --------
__device__ float g_qp[(size_t)MM * DD];
__device__ float g_kp[(size_t)MM * DD];
__device__ float g_vp[(size_t)MM * DD];
__device__ float g_ao[(size_t)MM * DD];

// ==================== helpers ================================================
__device__ __forceinline__ uint32_t f2tf32(float x) {
    uint32_t u;
    asm("cvt.rna.tf32.f32 %0, %1;" : "=r"(u) : "f"(x));
    return u;
}

// m16n8k8 tf32 mma (legacy tensor core; valid on compute_103 virtual arch)
__device__ __forceinline__ void mma_tf32(float* c, const uint32_t* a,
                                         const uint32_t* b) {
    asm volatile(
        "mma.sync.aligned.m16n8k8.row.col.f32.tf32.tf32.f32 "
        "{%0,%1,%2,%3}, {%4,%5,%6,%7}, {%8,%9}, {%0,%1,%2,%3};"
        : "+f"(c[0]), "+f"(c[1]), "+f"(c[2]), "+f"(c[3])
        : "r"(a[0]), "r"(a[1]), "r"(a[2]), "r"(a[3]), "r"(b[0]), "r"(b[1]));
}

// ==================== GEMM: C[M,N] = A[M,K] @ W[K,N] + bias ================
// (unchanged from Round 3 — passing, not yet profiled)
#define GTM 128
#define GTN 128
#define GKC 32
#define ALD 36
#define BLD 136
#define ABUF (GTM * ALD)
#define BBUF (GKC * BLD)
#define GSM_FLOATS (2 * (ABUF + BBUF))   // 71680 B

__global__ void __launch_bounds__(256)
gemm_mma(const float* __restrict__ A, const float* __restrict__ W,
         const float* __restrict__ bias, float* __restrict__ C) {
    extern __shared__ __align__(16) uint32_t gsm[];

    const int tid = threadIdx.x;
    const int wid = tid >> 5, lane = tid & 31;
    const int gid = lane >> 2, tg = lane & 3;
    const int bm = blockIdx.y * GTM, bn = blockIdx.x * GTN;
    const int wm = (wid >> 1) * 32, wn = (wid & 1) * 64;

    float acc[2][8][4];
#pragma unroll
    for (int mt = 0; mt < 2; mt++)
#pragma unroll
        for (int nt = 0; nt < 8; nt++)
#pragma unroll
            for (int c = 0; c < 4; c++) acc[mt][nt][c] = 0.0f;

    const int arow = tid >> 3, acol = (tid & 7) * 4;
    const int brow = tid >> 5, bcol = (tid & 31) * 4;

    float4 ar[4], br[4];

    auto loadAB = [&](int kc) {
        const float* ap = A + (size_t)(bm + arow) * GK + kc * GKC + acol;
#pragma unroll
        for (int i = 0; i < 4; i++)
            ar[i] = *(const float4*)(ap + (size_t)(32 * i) * GK);
        const float* bp = W + (size_t)(kc * GKC + brow) * DD + bn + bcol;
#pragma unroll
        for (int i = 0; i < 4; i++)
            br[i] = *(const float4*)(bp + (size_t)(8 * i) * DD);
    };

    auto storeAB = [&](int buf) {
        uint32_t* As = gsm + buf * ABUF;
        uint32_t* Bs = gsm + 2 * ABUF + buf * BBUF;
#pragma unroll
        for (int i = 0; i < 4; i++) {
            uint32_t* p = As + (arow + 32 * i) * ALD + acol;
            p[0] = f2tf32(ar[i].x); p[1] = f2tf32(ar[i].y);
            p[2] = f2tf32(ar[i].z); p[3] = f2tf32(ar[i].w);
        }
#pragma unroll
        for (int i = 0; i < 4; i++) {
            uint32_t* p = Bs + (brow + 8 * i) * BLD + bcol;
            p[0] = f2tf32(br[i].x); p[1] = f2tf32(br[i].y);
            p[2] = f2tf32(br[i].z); p[3] = f2tf32(br[i].w);
        }
    };

    auto compute = [&](int buf) {
        const uint32_t* As = gsm + buf * ABUF;
        const uint32_t* Bs = gsm + 2 * ABUF + buf * BBUF;
#pragma unroll
        for (int ks = 0; ks < 4; ks++) {
            const int k0 = ks * 8;
            uint32_t af[2][4], bf[8][2];
#pragma unroll
            for (int mt = 0; mt < 2; mt++) {
                const uint32_t* p = As + (wm + mt * 16 + gid) * ALD + k0 + tg;
                af[mt][0] = p[0];
                af[mt][1] = p[8 * ALD];
                af[mt][2] = p[4];
                af[mt][3] = p[8 * ALD + 4];
            }
#pragma unroll
            for (int nt = 0; nt < 8; nt++) {
                const uint32_t* p = Bs + (k0 + tg) * BLD + wn + nt * 8 + gid;
                bf[nt][0] = p[0];
                bf[nt][1] = p[4 * BLD];
            }
#pragma unroll
            for (int mt = 0; mt < 2; mt++)
#pragma unroll
                for (int nt = 0; nt < 8; nt++)
                    mma_tf32(acc[mt][nt], af[mt], bf[nt]);
        }
    };

    loadAB(0);
    storeAB(0);
    __syncthreads();
    for (int kc = 0; kc < GK / GKC; kc++) {
        const int buf = kc & 1;
        if (kc < GK / GKC - 1) loadAB(kc + 1);
        compute(buf);
        if (kc < GK / GKC - 1) storeAB(buf ^ 1);
        __syncthreads();
    }

#pragma unroll
    for (int mt = 0; mt < 2; mt++) {
        const int row = bm + wm + mt * 16 + gid;
#pragma unroll
        for (int nt = 0; nt < 8; nt++) {
            const int col = bn + wn + nt * 8 + 2 * tg;
            const float b0 = __ldg(bias + col), b1 = __ldg(bias + col + 1);
            float2 v0 = make_float2(acc[mt][nt][0] + b0, acc[mt][nt][1] + b1);
            float2 v1 = make_float2(acc[mt][nt][2] + b0, acc[mt][nt][3] + b1);
            *(float2*)(C + (size_t)row * DD + col) = v0;
            *(float2*)(C + (size_t)(row + 8) * DD + col) = v1;
        }
    }
}

// ==================== Flash attention on mma.sync tf32 ======================
// CTA: one (b, h, 128-q block). 4 warps, warp tile 32(q) x 64(k). BK=64.
// LDS/MMA = 1.5 (vs 2.5 in Round 3); 105.5 KB smem -> 2 CTA/SM.
#define FBQ 128
#define FQLD 68   // Q/K/P smem stride
#define FVLD 72   // V smem stride
#define FSM_FLOATS (FBQ * FQLD + 64 * FQLD + 64 * FVLD + FBQ * FQLD) // 26368

__global__ void __launch_bounds__(128)
flash_mma(const float* __restrict__ Qp, const float* __restrict__ Kp,
          const float* __restrict__ Vp, float* __restrict__ Op) {
    extern __shared__ __align__(16) uint32_t fsm[];
    uint32_t* Qs = fsm;                     // [128][68]
    uint32_t* Ks = Qs + FBQ * FQLD;         // [64][68]
    uint32_t* Vs = Ks + 64 * FQLD;          // [64][72]
    uint32_t* Ps = Vs + 64 * FVLD;          // [128][68]

    const int tid = threadIdx.x;
    const int wid = tid >> 5, lane = tid & 31;
    const int gid = lane >> 2, tg = lane & 3;
    const int q0 = blockIdx.x * FBQ;
    const int h = blockIdx.y, b = blockIdx.z;
    const size_t base = (size_t)b * SS * DD + (size_t)h * DKK;
    const int wm = wid * 32;

    // Load Q tile once, folding in 1/sqrt(dk)=0.125
    for (int i = tid; i < FBQ * 16; i += 128) {
        const int r = i >> 4, c = (i & 15) * 4;
        float4 v = *(const float4*)(Qp + base + (size_t)(q0 + r) * DD + c);
        uint32_t* p = Qs + r * FQLD + c;
        p[0] = f2tf32(v.x * 0.125f); p[1] = f2tf32(v.y * 0.125f);
        p[2] = f2tf32(v.z * 0.125f); p[3] = f2tf32(v.w * 0.125f);
    }

    float m_i[2][2], l_i[2][2];
    float oacc[2][8][4];
#pragma unroll
    for (int mt = 0; mt < 2; mt++) {
        m_i[mt][0] = -1e30f; m_i[mt][1] = -1e30f;
        l_i[mt][0] = 0.0f;   l_i[mt][1] = 0.0f;
#pragma unroll
        for (int nt = 0; nt < 8; nt++)
#pragma unroll
            for (int c = 0; c < 4; c++) oacc[mt][nt][c] = 0.0f;
    }

    for (int kb = 0; kb < SS / 64; kb++) {
        __syncthreads();   // prev PV done before overwriting Ks/Vs
        for (int i = tid; i < 64 * 16; i += 128) {
            const int r = i >> 4, c = (i & 15) * 4;
            const size_t g = base + (size_t)(kb * 64 + r) * DD + c;
            float4 kv = *(const float4*)(Kp + g);
            uint32_t* pk = Ks + r * FQLD + c;
            pk[0] = f2tf32(kv.x); pk[1] = f2tf32(kv.y);
            pk[2] = f2tf32(kv.z); pk[3] = f2tf32(kv.w);
            float4 vv = *(const float4*)(Vp + g);
            uint32_t* pv = Vs + r * FVLD + c;
            pv[0] = f2tf32(vv.x); pv[1] = f2tf32(vv.y);
            pv[2] = f2tf32(vv.z); pv[3] = f2tf32(vv.w);
        }
        __syncthreads();

        // S = Q @ K^T
        float s[2][8][4];
#pragma unroll
        for (int mt = 0; mt < 2; mt++)
#pragma unroll
            for (int nt = 0; nt < 8; nt++)
#pragma unroll
                for (int c = 0; c < 4; c++) s[mt][nt][c] = 0.0f;

#pragma unroll
        for (int ks = 0; ks < 8; ks++) {
            const int k0 = ks * 8;
            uint32_t af[2][4], bf[8][2];
#pragma unroll
            for (int mt = 0; mt < 2; mt++) {
                const uint32_t* ap = Qs + (wm + mt * 16 + gid) * FQLD + k0 + tg;
                af[mt][0] = ap[0];
                af[mt][1] = ap[8 * FQLD];
                af[mt][2] = ap[4];
                af[mt][3] = ap[8 * FQLD + 4];
            }
#pragma unroll
            for (int nt = 0; nt < 8; nt++) {
                const uint32_t* bp = Ks + (nt * 8 + gid) * FQLD + k0 + tg;
                bf[nt][0] = bp[0];
                bf[nt][1] = bp[4];
            }
#pragma unroll
            for (int mt = 0; mt < 2; mt++)
#pragma unroll
                for (int nt = 0; nt < 8; nt++)
                    mma_tf32(s[mt][nt], af[mt], bf[nt]);
        }

        // online softmax per mt (rows gid, gid+8 within 16-row subtile)
#pragma unroll
        for (int mt = 0; mt < 2; mt++) {
            float mx0 = -1e30f, mx1 = -1e30f;
#pragma unroll
            for (int nt = 0; nt < 8; nt++) {
                mx0 = fmaxf(mx0, fmaxf(s[mt][nt][0], s[mt][nt][1]));
                mx1 = fmaxf(mx1, fmaxf(s[mt][nt][2], s[mt][nt][3]));
            }
#pragma unroll
            for (int m = 1; m <= 2; m <<= 1) {
                mx0 = fmaxf(mx0, __shfl_xor_sync(0xffffffffu, mx0, m));
                mx1 = fmaxf(mx1, __shfl_xor_sync(0xffffffffu, mx1, m));
            }
            const float mn0 = fmaxf(m_i[mt][0], mx0);
            const float mn1 = fmaxf(m_i[mt][1], mx1);
            const float corr0 = __expf(m_i[mt][0] - mn0);
            const float corr1 = __expf(m_i[mt][1] - mn1);
            float sum0 = 0.0f, sum1 = 0.0f;
#pragma unroll
            for (int nt = 0; nt < 8; nt++) {
                s[mt][nt][0] = __expf(s[mt][nt][0] - mn0);
                s[mt][nt][1] = __expf(s[mt][nt][1] - mn0);
                s[mt][nt][2] = __expf(s[mt][nt][2] - mn1);
                s[mt][nt][3] = __expf(s[mt][nt][3] - mn1);
                sum0 += s[mt][nt][0] + s[mt][nt][1];
                sum1 += s[mt][nt][2] + s[mt][nt][3];
            }
#pragma unroll
            for (int m = 1; m <= 2; m <<= 1) {
                sum0 += __shfl_xor_sync(0xffffffffu, sum0, m);
                sum1 += __shfl_xor_sync(0xffffffffu, sum1, m);
            }
            l_i[mt][0] = l_i[mt][0] * corr0 + sum0;
            l_i[mt][1] = l_i[mt][1] * corr1 + sum1;
            m_i[mt][0] = mn0;
            m_i[mt][1] = mn1;
#pragma unroll
            for (int nt = 0; nt < 8; nt++) {
                oacc[mt][nt][0] *= corr0; oacc[mt][nt][1] *= corr0;
                oacc[mt][nt][2] *= corr1; oacc[mt][nt][3] *= corr1;
            }

            // write P fragments (C layout) to smem as tf32
#pragma unroll
            for (int nt = 0; nt < 8; nt++) {
                uint32_t* pp = Ps + (wm + mt * 16 + gid) * FQLD + nt * 8 + 2 * tg;
                pp[0] = f2tf32(s[mt][nt][0]);
                pp[1] = f2tf32(s[mt][nt][1]);
                pp[8 * FQLD] = f2tf32(s[mt][nt][2]);
                pp[8 * FQLD + 1] = f2tf32(s[mt][nt][3]);
            }
        }
        __syncwarp();

        // O += P @ V
#pragma unroll
        for (int ks = 0; ks < 8; ks++) {
            const int k0 = ks * 8;
            uint32_t af[2][4], bf[8][2];
#pragma unroll
            for (int mt = 0; mt < 2; mt++) {
                const uint32_t* ap = Ps + (wm + mt * 16 + gid) * FQLD + k0 + tg;
                af[mt][0] = ap[0];
                af[mt][1] = ap[8 * FQLD];
                af[mt][2] = ap[4];
                af[mt][3] = ap[8 * FQLD + 4];
            }
#pragma unroll
            for (int nt = 0; nt < 8; nt++) {
                const uint32_t* bp = Vs + (k0 + tg) * FVLD + nt * 8 + gid;
                bf[nt][0] = bp[0];
                bf[nt][1] = bp[4 * FVLD];
            }
#pragma unroll
            for (int mt = 0; mt < 2; mt++)
#pragma unroll
                for (int nt = 0; nt < 8; nt++)
                    mma_tf32(oacc[mt][nt], af[mt], bf[nt]);
        }
    }

    // epilogue: normalize, store
#pragma unroll
    for (int mt = 0; mt < 2; mt++) {
        const float inv0 = 1.0f / l_i[mt][0];
        const float inv1 = 1.0f / l_i[mt][1];
        const int row = q0 + wm + mt * 16 + gid;
#pragma unroll
        for (int nt = 0; nt < 8; nt++) {
            const int col = nt * 8 + 2 * tg;
            float2 v0 = make_float2(oacc[mt][nt][0] * inv0, oacc[mt][nt][1] * inv0);
            float2 v1 = make_float2(oacc[mt][nt][2] * inv1, oacc[mt][nt][3] * inv1);
            *(float2*)(Op + base + (size_t)row * DD + col) = v0;
            *(float2*)(Op + base + (size_t)(row + 8) * DD + col) = v1;
        }
    }
}

// ---------------- launch -----------------------------------------------------
extern "C" void kernel_launch(void* const* d_in, const int* in_sizes, int n_in,
                              void* d_out, int out_size) {
    (void)in_sizes; (void)n_in; (void)out_size;
    const float* q  = (const float*)d_in[0];
    const float* k  = (const float*)d_in[1];
    const float* v  = (const float*)d_in[2];
    const float* Wq = (const float*)d_in[3];
    const float* bq = (const float*)d_in[4];
    const float* Wk = (const float*)d_in[5];
    const float* bk = (const float*)d_in[6];
    const float* Wv = (const float*)d_in[7];
    const float* bv = (const float*)d_in[8];
    const float* Wo = (const float*)d_in[9];
    const float* bo = (const float*)d_in[10];
    float* out = (float*)d_out;

    float *qp, *kp, *vp, *ao;
    cudaGetSymbolAddress((void**)&qp, g_qp);
    cudaGetSymbolAddress((void**)&kp, g_kp);
    cudaGetSymbolAddress((void**)&vp, g_vp);
    cudaGetSymbolAddress((void**)&ao, g_ao);

    const int gsm_bytes = GSM_FLOATS * 4;   // 71680
    const int fsm_bytes = FSM_FLOATS * 4;   // 105472
    cudaFuncSetAttribute(gemm_mma, cudaFuncAttributeMaxDynamicSharedMemorySize,
                         gsm_bytes);
    cudaFuncSetAttribute(flash_mma, cudaFuncAttributeMaxDynamicSharedMemorySize,
                         fsm_bytes);

    dim3 gemm_grid(DD / GTN, MM / GTM);   // (8, 64)
    gemm_mma<<<gemm_grid, 256, gsm_bytes>>>(q, Wq, bq, qp);
    gemm_mma<<<gemm_grid, 256, gsm_bytes>>>(k, Wk, bk, kp);
    gemm_mma<<<gemm_grid, 256, gsm_bytes>>>(v, Wv, bv, vp);

    dim3 attn_grid(SS / FBQ, HH, BB);     // (16, 16, 4)
    flash_mma<<<attn_grid, 128, fsm_bytes>>>(qp, kp, vp, ao);

    gemm_mma<<<gemm_grid, 256, gsm_bytes>>>(ao, Wo, bo, out);
}